// round 4
// baseline (speedup 1.0000x reference)
#include <cuda_runtime.h>
#include <cuda_bf16.h>
#include <math.h>

// Problem constants
#define BB 4
#define NN 4096
#define DD 1024
#define EE 64
#define CAP 128
#define NTOK (BB * NN)   // 16384

// ---------------- scratch (no allocations allowed) ----------------
__device__ float g_logits[NTOK * EE];          // 4 MB
__device__ int   g_route[NTOK];                // idx1 | idx2<<6 | keep2<<12
__device__ float g_g1[NTOK];
__device__ float g_g2[NTOK];
__device__ unsigned char g_posk1[NTOK];        // 0xFF = dropped
__device__ unsigned char g_posk2[NTOK];
__device__ float g_dproxy[BB * EE];
__device__ int   g_dcount[BB * EE];
__device__ float g_zsum;

// ---------------- init accumulators ----------------
__global__ void init_kernel() {
    int i = threadIdx.x;
    if (i < BB * EE) { g_dproxy[i] = 0.0f; g_dcount[i] = 0; }
    if (i == 0) g_zsum = 0.0f;
}

// ---------------- GEMM: logits[16384,64] = x[16384,1024] @ w[1024,64] ----------------
// Block: 128 rows x 64 cols, K-tile 32, 256 threads, 8x4 per-thread tile.
__global__ __launch_bounds__(256) void gemm_kernel(const float* __restrict__ x,
                                                   const float* __restrict__ w) {
    __shared__ float xs[32][128];   // [k][m]
    __shared__ float ws[32][64];    // [k][n]
    const int m0 = blockIdx.x * 128;
    const int tid = threadIdx.x;
    const int r0 = (tid >> 4) * 8;   // row within tile
    const int c0 = (tid & 15) * 4;   // col within tile

    float acc[8][4];
#pragma unroll
    for (int i = 0; i < 8; i++)
#pragma unroll
        for (int j = 0; j < 4; j++) acc[i][j] = 0.0f;

    for (int k0 = 0; k0 < DD; k0 += 32) {
        // load x tile: 128 rows x 32 k  (1024 float4, 4 per thread), store transposed
#pragma unroll
        for (int i = 0; i < 4; i++) {
            int s = tid + i * 256;
            int row = s >> 3;
            int k4  = (s & 7) * 4;
            float4 v = *(const float4*)(x + (size_t)(m0 + row) * DD + k0 + k4);
            xs[k4 + 0][row] = v.x;
            xs[k4 + 1][row] = v.y;
            xs[k4 + 2][row] = v.z;
            xs[k4 + 3][row] = v.w;
        }
        // load w tile: 32 x 64 (512 float4, 2 per thread)
#pragma unroll
        for (int i = 0; i < 2; i++) {
            int s = tid + i * 256;
            int row = s >> 4;
            int c4  = (s & 15) * 4;
            *(float4*)&ws[row][c4] = *(const float4*)(w + (size_t)(k0 + row) * EE + c4);
        }
        __syncthreads();
#pragma unroll
        for (int kk = 0; kk < 32; kk++) {
            float a[8], b[4];
            *(float4*)&a[0] = *(const float4*)&xs[kk][r0];
            *(float4*)&a[4] = *(const float4*)&xs[kk][r0 + 4];
            *(float4*)&b[0] = *(const float4*)&ws[kk][c0];
#pragma unroll
            for (int i = 0; i < 8; i++)
#pragma unroll
                for (int j = 0; j < 4; j++) acc[i][j] = fmaf(a[i], b[j], acc[i][j]);
        }
        __syncthreads();
    }
#pragma unroll
    for (int i = 0; i < 8; i++) {
        float4 v = make_float4(acc[i][0], acc[i][1], acc[i][2], acc[i][3]);
        *(float4*)(g_logits + (size_t)(m0 + r0 + i) * EE + c0) = v;
    }
}

// ---------------- per-token softmax / top2 / stats ----------------
__global__ __launch_bounds__(256) void tokenstats_kernel() {
    const int t = blockIdx.x * 256 + threadIdx.x;   // token id (b*N + n)
    const int b = t >> 12;

    __shared__ float dps[EE];
    __shared__ int   dcs[EE];
    if (threadIdx.x < EE) { dps[threadIdx.x] = 0.0f; dcs[threadIdx.x] = 0; }
    __syncthreads();

    float l[EE];
#pragma unroll
    for (int i = 0; i < EE / 4; i++)
        *(float4*)&l[i * 4] = *(const float4*)(g_logits + (size_t)t * EE + i * 4);

    // top-1
    float m = l[0]; int i1 = 0;
#pragma unroll
    for (int e = 1; e < EE; e++)
        if (l[e] > m) { m = l[e]; i1 = e; }
    // sum exp
    float s = 0.0f;
#pragma unroll
    for (int e = 0; e < EE; e++) s += expf(l[e] - m);
    // top-2 (excluding i1)
    float m2 = -1e30f; int i2 = 0;
#pragma unroll
    for (int e = 0; e < EE; e++)
        if (e != i1 && l[e] > m2) { m2 = l[e]; i2 = e; }

    float inv_s = 1.0f / s;
    float g1 = inv_s;                 // exp(m - m)/s
    float g2 = expf(m2 - m) * inv_s;
    float denom = g1 + g2 + 1e-9f;
    float g1n = g1 / denom;
    float g2n = g2 / denom;
    int keep2 = (g2n > 0.2f) ? 1 : 0;

    g_route[t] = i1 | (i2 << 6) | (keep2 << 12);
    g_g1[t] = g1n;
    g_g2[t] = g2n;

    // density sums (per batch, per expert): raw_gates[e] = exp(l[e]-m)/s
#pragma unroll
    for (int e = 0; e < EE; e++) atomicAdd(&dps[e], expf(l[e] - m) * inv_s);
    atomicAdd(&dcs[i1], 1);

    // z-loss: logsumexp = m + log(s); warp-reduce then one atomic per warp
    float z = m + logf(s);
#pragma unroll
    for (int off = 16; off > 0; off >>= 1)
        z += __shfl_down_sync(0xFFFFFFFFu, z, off);
    if ((threadIdx.x & 31) == 0) atomicAdd(&g_zsum, z);

    __syncthreads();
    if (threadIdx.x < EE) {
        atomicAdd(&g_dproxy[b * EE + threadIdx.x], dps[threadIdx.x]);
        atomicAdd(&g_dcount[b * EE + threadIdx.x], dcs[threadIdx.x]);
    }
}

// ---------------- capacity scan: per batch exclusive cumsum with capacity ----------------
// 4 blocks (one per batch), 512 threads: e = tid&63, seg = tid>>6 (8 segs of 512 tokens)
__global__ __launch_bounds__(512) void scan_kernel() {
    const int b = blockIdx.x;
    __shared__ int sroute[NN];          // 16 KB
    __shared__ short c1s[8][EE];
    __shared__ short c2s[8][EE];
    const int tid = threadIdx.x;
    const int e = tid & 63;
    const int seg = tid >> 6;
    const int base = seg * 512;
    const int gbase = b * NN;

    for (int i = tid; i < NN; i += 512) sroute[i] = g_route[gbase + i];
    __syncthreads();

    int c1 = 0, c2 = 0;
    for (int t = 0; t < 512; t++) {
        int r = sroute[base + t];
        c1 += ((r & 63) == e);
        c2 += ((((r >> 6) & 63) == e) && (r >> 12));
    }
    c1s[seg][e] = (short)c1;
    c2s[seg][e] = (short)c2;
    __syncthreads();

    int pre1 = 0, tot1 = 0, pre2 = 0;
#pragma unroll
    for (int s2 = 0; s2 < 8; s2++) {
        int v1 = c1s[s2][e];
        int v2 = c2s[s2][e];
        tot1 += v1;
        if (s2 < seg) { pre1 += v1; pre2 += v2; }
    }
    int cap1 = tot1 < CAP ? tot1 : CAP;   // mask_1_count (post-capacity)
    int p1 = pre1;
    int p2 = cap1 + pre2;

    for (int t = 0; t < 512; t++) {
        int r = sroute[base + t];
        int gi = gbase + base + t;
        if ((r & 63) == e) {
            g_posk1[gi] = (p1 < CAP) ? (unsigned char)p1 : 0xFFu;
            p1++;
        }
        if (((r >> 6) & 63) == e) {
            if (r >> 12) {
                g_posk2[gi] = (p2 < CAP) ? (unsigned char)p2 : 0xFFu;
                p2++;
            } else {
                g_posk2[gi] = 0xFFu;
            }
        }
    }
}

// ---------------- scatter nonzeros into dispatch/combine ----------------
__global__ __launch_bounds__(256) void scatter_kernel(float* __restrict__ out, size_t cmb) {
    const int t = blockIdx.x * 256 + threadIdx.x;
    int r = g_route[t];
    int i1 = r & 63;
    int i2 = (r >> 6) & 63;
    unsigned p1 = g_posk1[t];
    unsigned p2 = g_posk2[t];
    size_t base = (size_t)t * (EE * CAP);
    if (p1 != 0xFFu) {
        size_t off = base + (size_t)i1 * CAP + p1;
        out[off] = 1.0f;
        out[cmb + off] = g_g1[t];
    }
    if (p2 != 0xFFu) {
        size_t off = base + (size_t)i2 * CAP + p2;
        out[off] = 1.0f;
        out[cmb + off] = g_g2[t];
    }
}

// ---------------- finalize scalars ----------------
__global__ void finalize_kernel(float* __restrict__ out, size_t cmb) {
    __shared__ float red[256];
    int i = threadIdx.x;   // 256 = BB*EE
    float v = g_dproxy[i] * (float)g_dcount[i];
    red[i] = v;
    __syncthreads();
    for (int s = 128; s > 0; s >>= 1) {
        if (i < s) red[i] += red[i + s];
        __syncthreads();
    }
    if (i == 0) {
        // loss = sum(dproxy_sum * count) * E / (B * N * N)
        float loss = red[0] * ((float)EE / ((float)BB * (float)NN * (float)NN));
        out[2 * cmb] = loss;
        out[2 * cmb + 1] = g_zsum / (float)BB;
    }
}

// ---------------- launch ----------------
extern "C" void kernel_launch(void* const* d_in, const int* in_sizes, int n_in,
                              void* d_out, int out_size) {
    const float* x = (const float*)d_in[0];
    const float* w = (const float*)d_in[1];
    float* out = (float*)d_out;
    size_t cmb = ((size_t)out_size - 2) / 2;   // 134,217,728

    // zero the whole output (dispatch/combine mostly zeros; scalars overwritten later)
    cudaMemsetAsync(d_out, 0, (size_t)out_size * sizeof(float), 0);

    init_kernel<<<1, 256>>>();
    gemm_kernel<<<NTOK / 128, 256>>>(x, w);
    tokenstats_kernel<<<NTOK / 256, 256>>>();
    scan_kernel<<<BB, 512>>>();
    scatter_kernel<<<NTOK / 256, 256>>>(out, cmb);
    finalize_kernel<<<1, 256>>>(out, cmb);
}

// round 5
// speedup vs baseline: 1.3847x; 1.3847x over previous
#include <cuda_runtime.h>
#include <cuda_bf16.h>
#include <math.h>

// Problem constants
#define BB 4
#define NN 4096
#define DD 1024
#define EE 64
#define CAP 128
#define NTOK (BB * NN)   // 16384

// ---------------- scratch (no allocations allowed) ----------------
__device__ int   g_route[NTOK];                // idx1 | idx2<<6 | keep2<<12
__device__ float g_g1[NTOK];
__device__ float g_g2[NTOK];
__device__ float g_dproxy[BB * EE];
__device__ int   g_dcount[BB * EE];
__device__ float g_zsum;

// ---------------- init accumulators ----------------
__global__ void init_kernel() {
    int i = threadIdx.x;
    if (i < BB * EE) { g_dproxy[i] = 0.0f; g_dcount[i] = 0; }
    if (i == 0) g_zsum = 0.0f;
}

// ============================================================================
// Fused kernel: zero the 1.07GB output (interleaved streaming stores) +
// GEMM logits[128,64] tile + softmax/top2/route/density/z-loss epilogue.
// Block: 128 tokens x 64 experts, K-tile 32, 256 threads, 8x4 per-thread tile.
// The zero stores (DRAM-write bound, ~150us chip-wide) hide the GEMM compute.
// ============================================================================
__global__ __launch_bounds__(256) void gemm_fused_kernel(const float* __restrict__ x,
                                                         const float* __restrict__ w,
                                                         float* __restrict__ out) {
    // Union: K-loop uses xs[32][128] + ws[32][64] (6144 floats);
    // epilogue reuses the same buffer as lbuf[128][65] (8320 floats).
    __shared__ __align__(16) float sbuf[128 * 65];
    float (*xs)[128] = reinterpret_cast<float(*)[128]>(sbuf);
    float (*ws)[64]  = reinterpret_cast<float(*)[64]>(sbuf + 32 * 128);
    __shared__ float dps[EE];
    __shared__ int   dcs[EE];

    const int m0 = blockIdx.x * 128;
    const int tid = threadIdx.x;
    const int r0 = (tid >> 4) * 8;   // row within tile
    const int c0 = (tid & 15) * 4;   // col within tile

    if (tid < EE) { dps[tid] = 0.0f; dcs[tid] = 0; }

    // zero-store setup: this block owns out4[base4 .. base4+524288)
    float4* out4 = reinterpret_cast<float4*>(out);
    const size_t base4 = (size_t)blockIdx.x * 524288u;
    const float4 z4 = make_float4(0.f, 0.f, 0.f, 0.f);

    float acc[8][4];
#pragma unroll
    for (int i = 0; i < 8; i++)
#pragma unroll
        for (int j = 0; j < 4; j++) acc[i][j] = 0.0f;

    for (int k0 = 0; k0 < DD; k0 += 32) {
        // load x tile: 128 rows x 32 k (transposed into smem)
#pragma unroll
        for (int i = 0; i < 4; i++) {
            int s = tid + i * 256;
            int row = s >> 3;
            int k4  = (s & 7) * 4;
            float4 v = *(const float4*)(x + (size_t)(m0 + row) * DD + k0 + k4);
            xs[k4 + 0][row] = v.x;
            xs[k4 + 1][row] = v.y;
            xs[k4 + 2][row] = v.z;
            xs[k4 + 3][row] = v.w;
        }
        // load w tile: 32 x 64
#pragma unroll
        for (int i = 0; i < 2; i++) {
            int s = tid + i * 256;
            int row = s >> 4;
            int c4  = (s & 15) * 4;
            *(float4*)&ws[row][c4] = *(const float4*)(w + (size_t)(k0 + row) * EE + c4);
        }
        __syncthreads();
#pragma unroll
        for (int kk = 0; kk < 32; kk++) {
            float a[8], b[4];
            *(float4*)&a[0] = *(const float4*)&xs[kk][r0];
            *(float4*)&a[4] = *(const float4*)&xs[kk][r0 + 4];
            *(float4*)&b[0] = *(const float4*)&ws[kk][c0];
#pragma unroll
            for (int i = 0; i < 8; i++)
#pragma unroll
                for (int j = 0; j < 4; j++) acc[i][j] = fmaf(a[i], b[j], acc[i][j]);
        }
        // interleave 64 streaming zero-stores per thread per K-tile (fire-and-forget)
        {
            const int iter = k0 >> 5;               // 0..31
            size_t b4 = base4 + ((size_t)iter * 64 << 8) + tid;
#pragma unroll 8
            for (int j = 0; j < 64; j++) {
                __stcs(out4 + b4, z4);
                b4 += 256;
            }
        }
        __syncthreads();
    }

    // ---- epilogue: logits -> smem (overwrites dead tiles; sync above protects) ----
    float (*lbuf)[65] = reinterpret_cast<float(*)[65]>(sbuf);
#pragma unroll
    for (int i = 0; i < 8; i++)
#pragma unroll
        for (int j = 0; j < 4; j++) lbuf[r0 + i][c0 + j] = acc[i][j];
    __syncthreads();

    if (tid < 128) {
        const int t = m0 + tid;   // token id

        // top-1 (lowest index on ties, matching argmax)
        float m = lbuf[tid][0]; int i1 = 0;
#pragma unroll
        for (int e = 1; e < EE; e++) {
            float v = lbuf[tid][e];
            if (v > m) { m = v; i1 = e; }
        }
        // top-2 excluding i1
        float m2 = -1e30f; int i2 = 0;
#pragma unroll
        for (int e = 0; e < EE; e++) {
            float v = lbuf[tid][e];
            if (e != i1 && v > m2) { m2 = v; i2 = e; }
        }
        // softmax: overwrite logits row with exp(l-m), accumulate sum
        float s = 0.0f;
#pragma unroll
        for (int e = 0; e < EE; e++) {
            float p = expf(lbuf[tid][e] - m);
            lbuf[tid][e] = p;
            s += p;
        }
        float inv_s = 1.0f / s;
        float g1 = inv_s;                       // exp(m-m)/s
        float g2 = lbuf[tid][i2] * inv_s;       // exp(m2-m)/s
        float denom = g1 + g2 + 1e-9f;
        float g1n = g1 / denom;
        float g2n = g2 / denom;
        int keep2 = (g2n > 0.2f) ? 1 : 0;

        g_route[t] = i1 | (i2 << 6) | (keep2 << 12);
        g_g1[t] = g1n;
        g_g2[t] = g2n;

        // density: rotated offsets -> conflict-free shared atomics
        int lane = tid & 31;
#pragma unroll
        for (int k = 0; k < EE; k++) {
            int e = (lane + k) & 63;
            atomicAdd(&dps[e], lbuf[tid][e] * inv_s);
        }
        atomicAdd(&dcs[i1], 1);

        // z-loss: warp reduce then one global atomic per warp
        float zz = m + logf(s);
#pragma unroll
        for (int off = 16; off > 0; off >>= 1)
            zz += __shfl_down_sync(0xFFFFFFFFu, zz, off);
        if (lane == 0) atomicAdd(&g_zsum, zz);
    }
    __syncthreads();
    if (tid < EE) {
        int b = m0 >> 12;   // batch of this block's tokens
        atomicAdd(&g_dproxy[b * EE + tid], dps[tid]);
        atomicAdd(&g_dcount[b * EE + tid], dcs[tid]);
    }
}

// ============================================================================
// Capacity scan + scatter: per batch, exclusive cumsum over tokens with
// capacity truncation, using warp match_any ranking (O(1) per token) and a
// two-level ushort prefix over 128 groups of 32 tokens. Writes the nonzero
// dispatch/combine entries directly.
// ============================================================================
__global__ __launch_bounds__(1024) void scan_scatter_kernel(float* __restrict__ out,
                                                            size_t cmb) {
    const int b = blockIdx.x;
    __shared__ unsigned short c1[128][EE];   // 16 KB: counts -> exclusive prefix
    __shared__ unsigned short c2[128][EE];   // 16 KB
    __shared__ int part1[8][EE];
    __shared__ int part2[8][EE];
    __shared__ unsigned short tot1s[EE];     // min(batch top-1 count, CAP)

    const int tid = threadIdx.x;
    const int lane = tid & 31;
    const int wrp = tid >> 5;
    const unsigned lt = (1u << lane) - 1u;

    for (int i = tid; i < 128 * EE; i += 1024) {
        ((unsigned short*)c1)[i] = 0;
        ((unsigned short*)c2)[i] = 0;
    }
    __syncthreads();

    // phase 1: per-group counts + per-token ranks via match_any
    int rr[4], rk1[4], rk2[4];
#pragma unroll
    for (int i = 0; i < 4; i++) {
        int g = wrp * 4 + i;
        int t = b * NN + g * 32 + lane;
        int r = g_route[t];
        rr[i] = r;
        int e1 = r & 63, e2 = (r >> 6) & 63, k2 = r >> 12;
        unsigned m1 = __match_any_sync(0xFFFFFFFFu, e1);
        rk1[i] = __popc(m1 & lt);
        if ((m1 & lt) == 0) c1[g][e1] = (unsigned short)__popc(m1);
        unsigned bal = __ballot_sync(0xFFFFFFFFu, k2);
        unsigned m2 = __match_any_sync(0xFFFFFFFFu, e2) & bal;
        rk2[i] = __popc(m2 & lt);
        if (k2 && ((m2 & lt) == 0)) c2[g][e2] = (unsigned short)__popc(m2);
    }
    __syncthreads();

    // phase 2: in-place exclusive prefix over the 128 groups, per expert.
    // thread (e, chunk): 64 experts x 8 chunks of 16 groups.
    if (tid < 512) {
        int e = tid & 63, c = tid >> 6;
        int s1 = 0, s2 = 0;
#pragma unroll
        for (int j = 0; j < 16; j++) { s1 += c1[c * 16 + j][e]; s2 += c2[c * 16 + j][e]; }
        part1[c][e] = s1; part2[c][e] = s2;
    }
    __syncthreads();
    if (tid < 512) {
        int e = tid & 63, c = tid >> 6;
        int off1 = 0, off2 = 0;
#pragma unroll
        for (int cc = 0; cc < 8; cc++)
            if (cc < c) { off1 += part1[cc][e]; off2 += part2[cc][e]; }
        if (c == 7) {
            int tt = off1 + part1[7][e];
            tot1s[e] = (unsigned short)(tt < CAP ? tt : CAP);
        }
        int run1 = off1, run2 = off2;
#pragma unroll
        for (int j = 0; j < 16; j++) {
            int g = c * 16 + j;
            int v1 = c1[g][e]; c1[g][e] = (unsigned short)run1; run1 += v1;
            int v2 = c2[g][e]; c2[g][e] = (unsigned short)run2; run2 += v2;
        }
    }
    __syncthreads();

    // phase 3: positions + direct scatter of nonzeros
#pragma unroll
    for (int i = 0; i < 4; i++) {
        int g = wrp * 4 + i;
        int t = b * NN + g * 32 + lane;
        int r = rr[i];
        int e1 = r & 63, e2 = (r >> 6) & 63, k2 = r >> 12;
        size_t tb = (size_t)t * (EE * CAP);

        int p1 = (int)c1[g][e1] + rk1[i];
        if (p1 < CAP) {
            size_t off = tb + (size_t)e1 * CAP + p1;
            out[off] = 1.0f;
            out[cmb + off] = g_g1[t];
        }
        if (k2) {
            int p2 = (int)tot1s[e2] + (int)c2[g][e2] + rk2[i];
            if (p2 < CAP) {
                size_t off = tb + (size_t)e2 * CAP + p2;
                out[off] = 1.0f;
                out[cmb + off] = g_g2[t];
            }
        }
    }
}

// ---------------- finalize scalars ----------------
__global__ void finalize_kernel(float* __restrict__ out, size_t cmb) {
    __shared__ float red[256];
    int i = threadIdx.x;   // 256 = BB*EE
    float v = g_dproxy[i] * (float)g_dcount[i];
    red[i] = v;
    __syncthreads();
    for (int s = 128; s > 0; s >>= 1) {
        if (i < s) red[i] += red[i + s];
        __syncthreads();
    }
    if (i == 0) {
        float loss = red[0] * ((float)EE / ((float)BB * (float)NN * (float)NN));
        out[2 * cmb] = loss;
        out[2 * cmb + 1] = g_zsum / (float)BB;
    }
}

// ---------------- launch ----------------
extern "C" void kernel_launch(void* const* d_in, const int* in_sizes, int n_in,
                              void* d_out, int out_size) {
    const float* x = (const float*)d_in[0];
    const float* w = (const float*)d_in[1];
    float* out = (float*)d_out;
    size_t cmb = ((size_t)out_size - 2) / 2;   // 134,217,728

    init_kernel<<<1, 256>>>();
    gemm_fused_kernel<<<NTOK / 128, 256>>>(x, w, out);   // zeroes out + logits + routing stats
    scan_scatter_kernel<<<BB, 1024>>>(out, cmb);
    finalize_kernel<<<1, 256>>>(out, cmb);
}